// round 9
// baseline (speedup 1.0000x reference)
#include <cuda_runtime.h>
#include <cuda_bf16.h>

#define H 256
#define F_MAX 300032          // >= 3*N-8 for N=100000, float4-aligned
#define CT 512                // columns per pipeline tile
#define RB 8                  // rows per block (warp per row)
#define NS 18                 // column splits
#define NRG (H / RB)          // 32 row groups
#define GRID (NRG * NS)       // 576 blocks = one resident wave at 4/SM
#define STG 3                 // pipeline stages
#define W_CHUNKS (RB * CT / 4)            // 1024 float4 per stage (W)
#define X_CHUNKS (CT / 4)                 // 128 float4 per stage (x)
#define SMEM_BYTES (STG * (W_CHUNKS + X_CHUNKS) * 16)   // 55296 B

// Scratch (no allocations allowed in kernel_launch)
__device__ __align__(16) float g_x[F_MAX];
__device__ float g_partial[NS * H];   // [colsplit][row] -> coalesced reduce
__device__ unsigned g_ready = 0;      // monotonic epoch counter (replay-safe)

// ---------------------------------------------------------------------------
// cp.async 16B helper (predicated)
// ---------------------------------------------------------------------------
__device__ __forceinline__ void cp16(void* smem_dst, const void* gmem_src, int pred) {
    unsigned s = (unsigned)__cvta_generic_to_shared(smem_dst);
    asm volatile(
        "{ .reg .pred p;\n"
        "  setp.ne.b32 p, %0, 0;\n"
        "  @p cp.async.cg.shared.global [%1], [%2], 16;\n"
        "}" :: "r"(pred), "r"(s), "l"(gmem_src));
}
__device__ __forceinline__ void cp_commit() {
    asm volatile("cp.async.commit_group;");
}

// ---------------------------------------------------------------------------
// Fused kernel: W-prefetch -> featurization -> grid gate -> GEMV pipeline.
// ---------------------------------------------------------------------------
__global__ void __launch_bounds__(256, 4) fused_kernel(
        const float* __restrict__ pos,
        const int* __restrict__ aidx,
        const int* __restrict__ didx,
        const float* __restrict__ W1,
        int A, int D, int F, int TT) {
    extern __shared__ __align__(16) float4 smem[];
    float4* wsb = smem;                          // STG * W_CHUNKS
    float4* xsb = smem + STG * W_CHUNKS;         // STG * X_CHUNKS

    int bid = blockIdx.x;
    int rg = bid & (NRG - 1);          // row group (32)
    int cs = bid / NRG;                // column split (18)
    int rowbase = rg * RB;

    int base = TT / NS, rem = TT % NS;
    int t0 = cs * base + (cs < rem ? cs : rem);
    int t1 = t0 + base + (cs < rem ? 1 : 0);

    int tid = threadIdx.x;
    int warp = tid >> 5, lane = tid & 31;

    auto issueW = [&](int s, int tile) {
        int c0 = tile * CT;
        int nc4 = (F - c0 >= CT) ? X_CHUNKS : ((F - c0) >> 2);
        float4* ws = wsb + s * W_CHUNKS;
#pragma unroll
        for (int k = 0; k < 4; k++) {
            int c = tid + k * 256;
            int row = c >> 7;
            int off = c & 127;
            cp16(&ws[c],
                 W1 + (size_t)(rowbase + row) * F + c0 + off * 4,
                 off < nc4);
        }
    };
    auto issueX = [&](int s, int tile) {
        int c0 = tile * CT;
        int nc4 = (F - c0 >= CT) ? X_CHUNKS : ((F - c0) >> 2);
        float4* xs = xsb + s * X_CHUNKS;
        if (tid < X_CHUNKS)
            cp16(&xs[tid], g_x + c0 + tid * 4, tid < nc4);
    };

    // ---- (1) W prefetch: start the DRAM stream before feature work ----
    issueW(0, t0);
    if (t0 + 1 < t1) issueW(1, t0 + 1);
    cp_commit();                                   // G0

    // ---- (2) featurization (grid-stride over A + D tasks) ----
    for (int t = bid * 256 + tid; t < A + D; t += GRID * 256) {
        if (t < A) {
            int i0 = aidx[3 * t + 0], i1 = aidx[3 * t + 1], i2 = aidx[3 * t + 2];
            float p0x = pos[3 * i0], p0y = pos[3 * i0 + 1], p0z = pos[3 * i0 + 2];
            float p1x = pos[3 * i1], p1y = pos[3 * i1 + 1], p1z = pos[3 * i1 + 2];
            float p2x = pos[3 * i2], p2y = pos[3 * i2 + 1], p2z = pos[3 * i2 + 2];
            float v0x = p0x - p1x, v0y = p0y - p1y, v0z = p0z - p1z;
            float v1x = p2x - p1x, v1y = p2y - p1y, v1z = p2z - p1z;
            float d = v0x * v1x + v0y * v1y + v0z * v1z;
            float cx = v0y * v1z - v0z * v1y;
            float cy = v0z * v1x - v0x * v1z;
            float cz = v0x * v1y - v0y * v1x;
            float cr2 = cx * cx + cy * cy + cz * cz;
            g_x[t] = d * rsqrtf(fmaf(d, d, cr2));
        } else {
            int j = t - A;
            int i0 = didx[4 * j + 0], i1 = didx[4 * j + 1];
            int i2 = didx[4 * j + 2], i3 = didx[4 * j + 3];
            float p0x = pos[3 * i0], p0y = pos[3 * i0 + 1], p0z = pos[3 * i0 + 2];
            float p1x = pos[3 * i1], p1y = pos[3 * i1 + 1], p1z = pos[3 * i1 + 2];
            float p2x = pos[3 * i2], p2y = pos[3 * i2 + 1], p2z = pos[3 * i2 + 2];
            float p3x = pos[3 * i3], p3y = pos[3 * i3 + 1], p3z = pos[3 * i3 + 2];
            float b1x = p1x - p0x, b1y = p1y - p0y, b1z = p1z - p0z;
            float b2x = p2x - p1x, b2y = p2y - p1y, b2z = p2z - p1z;
            float b3x = p3x - p2x, b3y = p3y - p2y, b3z = p3z - p2z;
            float n1x = b1y * b2z - b1z * b2y;
            float n1y = b1z * b2x - b1x * b2z;
            float n1z = b1x * b2y - b1y * b2x;
            float n2x = b2y * b3z - b2z * b3y;
            float n2y = b2z * b3x - b2x * b3z;
            float n2z = b2x * b3y - b2y * b3x;
            float xd = n1x * n2x + n1y * n2y + n1z * n2z;
            float mx = n1y * n2z - n1z * n2y;
            float my = n1z * n2x - n1x * n2z;
            float mz = n1x * n2y - n1y * n2x;
            float b2n2 = b2x * b2x + b2y * b2y + b2z * b2z;
            float yd = (mx * b2x + my * b2y + mz * b2z) * rsqrtf(b2n2);
            float r = rsqrtf(fmaf(xd, xd, yd * yd));
            g_x[A + j]     = xd * r;   // cos(dihedral)
            g_x[A + D + j] = yd * r;   // sin(dihedral)
        }
    }

    // ---- (3) grid gate: all 576 blocks resident (one wave), epoch counter ----
    __threadfence();
    __syncthreads();
    if (tid == 0) {
        unsigned arrive = atomicAdd(&g_ready, 1u);        // 0-based global order
        unsigned target = (arrive / GRID + 1u) * GRID;    // my epoch's finish line
        while (*(volatile unsigned*)&g_ready < target) { __nanosleep(32); }
        __threadfence();
    }
    __syncthreads();

    // ---- (4) x prefetch for first two tiles ----
    issueX(0, t0);
    if (t0 + 1 < t1) issueX(1, t0 + 1);
    cp_commit();                                   // G1

    // ---- (5) GEMV pipeline: wait -> sync -> issue(t+2) -> compute(t) ----
    float a0 = 0.f, a1 = 0.f, a2 = 0.f, a3 = 0.f;

    for (int t = t0; t < t1; t++) {
        int cur = (t - t0) % STG;
        if (t == t0 || t == t1 - 1) asm volatile("cp.async.wait_group 0;");
        else                        asm volatile("cp.async.wait_group 1;");
        __syncthreads();             // tile t visible; compute(t-1) done by all
        if (t + 2 < t1) {            // overwrites buffer of tile t-1
            issueW((cur + 2) % STG, t + 2);
            issueX((cur + 2) % STG, t + 2);
            cp_commit();
        }

        const float4* ws = wsb + cur * W_CHUNKS + warp * X_CHUNKS;
        const float4* xs = xsb + cur * X_CHUNKS;
        int c0 = t * CT;
        if (F - c0 >= CT) {          // full tile: predicate-free
#pragma unroll
            for (int k = 0; k < 4; k++) {
                int i = lane + 32 * k;
                float4 wv = ws[i];
                float4 xv = xs[i];
                a0 = fmaf(wv.x, xv.x, a0);
                a1 = fmaf(wv.y, xv.y, a1);
                a2 = fmaf(wv.z, xv.z, a2);
                a3 = fmaf(wv.w, xv.w, a3);
            }
        } else {                     // ragged last tile
            int nc4 = (F - c0) >> 2;
#pragma unroll
            for (int k = 0; k < 4; k++) {
                int i = lane + 32 * k;
                if (i < nc4) {
                    float4 wv = ws[i];
                    float4 xv = xs[i];
                    a0 = fmaf(wv.x, xv.x, a0);
                    a1 = fmaf(wv.y, xv.y, a1);
                    a2 = fmaf(wv.z, xv.z, a2);
                    a3 = fmaf(wv.w, xv.w, a3);
                }
            }
        }
    }

    float acc = (a0 + a2) + (a1 + a3);
#pragma unroll
    for (int o = 16; o; o >>= 1) acc += __shfl_xor_sync(0xffffffffu, acc, o);
    if (lane == 0) g_partial[cs * H + rowbase + warp] = acc;
}

// ---------------------------------------------------------------------------
// Kernel 2: deterministic reduce + b1 + tanh, then the two 256x256 layers and
// the final W4 dot. One block of 1024 threads (32 warps -> 8 rows/warp/layer).
// ---------------------------------------------------------------------------
__global__ void __launch_bounds__(1024) mlp_kernel(const float* __restrict__ b1,
                                                   const float* __restrict__ W2,
                                                   const float* __restrict__ b2,
                                                   const float* __restrict__ W3,
                                                   const float* __restrict__ b3,
                                                   const float* __restrict__ W4,
                                                   float* __restrict__ out) {
    __shared__ float sa[H], sb[H];
    int tid = threadIdx.x;
    int warp = tid >> 5, lane = tid & 31;

    if (tid < H) {
        float acc = 0.f;
#pragma unroll
        for (int k = 0; k < NS; k++) acc += g_partial[k * H + tid];
        sa[tid] = tanhf(acc + b1[tid]);
    }
    __syncthreads();

#pragma unroll
    for (int h = warp; h < H; h += 32) {
        const float* Wr = W2 + h * H;
        float a = 0.f;
#pragma unroll
        for (int k = 0; k < 8; k++) a += Wr[lane + 32 * k] * sa[lane + 32 * k];
#pragma unroll
        for (int o = 16; o; o >>= 1) a += __shfl_xor_sync(0xffffffffu, a, o);
        if (lane == 0) sb[h] = tanhf(a + b2[h]);
    }
    __syncthreads();

#pragma unroll
    for (int h = warp; h < H; h += 32) {
        const float* Wr = W3 + h * H;
        float a = 0.f;
#pragma unroll
        for (int k = 0; k < 8; k++) a += Wr[lane + 32 * k] * sb[lane + 32 * k];
#pragma unroll
        for (int o = 16; o; o >>= 1) a += __shfl_xor_sync(0xffffffffu, a, o);
        if (lane == 0) sa[h] = tanhf(a + b3[h]);
    }
    __syncthreads();

    if (warp == 0) {
        float a = 0.f;
#pragma unroll
        for (int k = 0; k < 8; k++) a += W4[lane + 32 * k] * sa[lane + 32 * k];
#pragma unroll
        for (int o = 16; o; o >>= 1) a += __shfl_xor_sync(0xffffffffu, a, o);
        if (lane == 0) out[0] = 0.00831446261815324f * 300.0f * a;
    }
}

// ---------------------------------------------------------------------------
extern "C" void kernel_launch(void* const* d_in, const int* in_sizes, int n_in,
                              void* d_out, int out_size) {
    const float* pos  = (const float*)d_in[0];
    const int*   aidx = (const int*)  d_in[1];
    const int*   didx = (const int*)  d_in[2];
    const float* W1   = (const float*)d_in[3];
    const float* b1   = (const float*)d_in[4];
    const float* W2   = (const float*)d_in[5];
    const float* b2   = (const float*)d_in[6];
    const float* W3   = (const float*)d_in[7];
    const float* b3   = (const float*)d_in[8];
    const float* W4   = (const float*)d_in[9];

    int A = in_sizes[1] / 3;
    int D = in_sizes[2] / 4;
    int F = A + 2 * D;
    int TT = (F + CT - 1) / CT;          // 586 tiles for N=100000

    cudaFuncSetAttribute(fused_kernel,
                         cudaFuncAttributeMaxDynamicSharedMemorySize, SMEM_BYTES);

    fused_kernel<<<GRID, 256, SMEM_BYTES>>>(pos, aidx, didx, W1, A, D, F, TT);
    mlp_kernel<<<1, 1024>>>(b1, W2, b2, W3, b3, W4, (float*)d_out);
}

// round 10
// speedup vs baseline: 1.1223x; 1.1223x over previous
#include <cuda_runtime.h>
#include <cuda_bf16.h>

#define H 256
#define F_MAX 300032          // >= 3*N-8 for N=100000, float4-aligned
#define CT 512                // columns per pipeline tile
#define RB 8                  // rows per block (warp per row)
#define NS 18                 // column splits
#define NRG (H / RB)          // 32 row groups
#define STG 3                 // pipeline stages
#define W_CHUNKS (RB * CT / 4)            // 1024 float4 per stage (W)
#define X_CHUNKS (CT / 4)                 // 128 float4 per stage (x)
#define SMEM_BYTES (STG * (W_CHUNKS + X_CHUNKS) * 16)   // 55296 B

// Scratch (no allocations allowed in kernel_launch)
__device__ __align__(16) float g_x[F_MAX];
__device__ float g_partial[NS * H];   // [colsplit][row] -> coalesced reduce

// ---------------------------------------------------------------------------
// cp.async 16B helper (predicated)
// ---------------------------------------------------------------------------
__device__ __forceinline__ void cp16(void* smem_dst, const void* gmem_src, int pred) {
    unsigned s = (unsigned)__cvta_generic_to_shared(smem_dst);
    asm volatile(
        "{ .reg .pred p;\n"
        "  setp.ne.b32 p, %0, 0;\n"
        "  @p cp.async.cg.shared.global [%1], [%2], 16;\n"
        "}" :: "r"(pred), "r"(s), "l"(gmem_src));
}
__device__ __forceinline__ void cp_commit() {
    asm volatile("cp.async.commit_group;");
}
__device__ __forceinline__ void prefetchL2(const void* p) {
    asm volatile("prefetch.global.L2 [%0];" :: "l"(p));
}

// ---------------------------------------------------------------------------
// Kernel 1: featurization. x = [cos(angles) | cos(dihedrals) | sin(dihedrals)]
// ---------------------------------------------------------------------------
__global__ void feat_kernel(const float* __restrict__ pos,
                            const int* __restrict__ aidx,
                            const int* __restrict__ didx,
                            int A, int D) {
    int t = blockIdx.x * blockDim.x + threadIdx.x;
    if (t < A) {
        int i0 = aidx[3 * t + 0], i1 = aidx[3 * t + 1], i2 = aidx[3 * t + 2];
        float p0x = pos[3 * i0], p0y = pos[3 * i0 + 1], p0z = pos[3 * i0 + 2];
        float p1x = pos[3 * i1], p1y = pos[3 * i1 + 1], p1z = pos[3 * i1 + 2];
        float p2x = pos[3 * i2], p2y = pos[3 * i2 + 1], p2z = pos[3 * i2 + 2];
        float v0x = p0x - p1x, v0y = p0y - p1y, v0z = p0z - p1z;
        float v1x = p2x - p1x, v1y = p2y - p1y, v1z = p2z - p1z;
        float d = v0x * v1x + v0y * v1y + v0z * v1z;
        float cx = v0y * v1z - v0z * v1y;
        float cy = v0z * v1x - v0x * v1z;
        float cz = v0x * v1y - v0y * v1x;
        float cr2 = cx * cx + cy * cy + cz * cz;
        g_x[t] = d * rsqrtf(fmaf(d, d, cr2));
    } else if (t < A + D) {
        int j = t - A;
        int i0 = didx[4 * j + 0], i1 = didx[4 * j + 1];
        int i2 = didx[4 * j + 2], i3 = didx[4 * j + 3];
        float p0x = pos[3 * i0], p0y = pos[3 * i0 + 1], p0z = pos[3 * i0 + 2];
        float p1x = pos[3 * i1], p1y = pos[3 * i1 + 1], p1z = pos[3 * i1 + 2];
        float p2x = pos[3 * i2], p2y = pos[3 * i2 + 1], p2z = pos[3 * i2 + 2];
        float p3x = pos[3 * i3], p3y = pos[3 * i3 + 1], p3z = pos[3 * i3 + 2];
        float b1x = p1x - p0x, b1y = p1y - p0y, b1z = p1z - p0z;
        float b2x = p2x - p1x, b2y = p2y - p1y, b2z = p2z - p1z;
        float b3x = p3x - p2x, b3y = p3y - p2y, b3z = p3z - p2z;
        float n1x = b1y * b2z - b1z * b2y;
        float n1y = b1z * b2x - b1x * b2z;
        float n1z = b1x * b2y - b1y * b2x;
        float n2x = b2y * b3z - b2z * b3y;
        float n2y = b2z * b3x - b2x * b3z;
        float n2z = b2x * b3y - b2y * b3x;
        float xd = n1x * n2x + n1y * n2y + n1z * n2z;
        float mx = n1y * n2z - n1z * n2y;
        float my = n1z * n2x - n1x * n2z;
        float mz = n1x * n2y - n1y * n2x;
        float b2n2 = b2x * b2x + b2y * b2y + b2z * b2z;
        float yd = (mx * b2x + my * b2y + mz * b2z) * rsqrtf(b2n2);
        float r = rsqrtf(fmaf(xd, xd, yd * yd));
        g_x[A + j]     = xd * r;   // cos(dihedral)
        g_x[A + D + j] = yd * r;   // sin(dihedral)
    }
}

// ---------------------------------------------------------------------------
// Kernel 2: GEMV partials via 3-stage cp.async pipeline, one barrier per tile.
// (unchanged from R8: measured ~45us = ~6.8 TB/s on the 307MB W1 stream)
// ---------------------------------------------------------------------------
__global__ void __launch_bounds__(256) gemv_kernel(const float* __restrict__ W1,
                                                   int F, int TT) {
    extern __shared__ __align__(16) float4 smem[];
    float4* wsb = smem;                          // STG * W_CHUNKS
    float4* xsb = smem + STG * W_CHUNKS;         // STG * X_CHUNKS

    int bid = blockIdx.x;
    int rg = bid & (NRG - 1);          // row group (32)
    int cs = bid / NRG;                // column split (18)
    int rowbase = rg * RB;

    int base = TT / NS, rem = TT % NS;
    int t0 = cs * base + (cs < rem ? cs : rem);
    int t1 = t0 + base + (cs < rem ? 1 : 0);

    int tid = threadIdx.x;
    int warp = tid >> 5, lane = tid & 31;

    auto issue = [&](int s, int tile) {
        int c0 = tile * CT;
        int ncols = F - c0; if (ncols > CT) ncols = CT;
        int nc4 = ncols >> 2;
        float4* ws = wsb + s * W_CHUNKS;
        float4* xs = xsb + s * X_CHUNKS;
#pragma unroll
        for (int k = 0; k < 4; k++) {
            int c = tid + k * 256;
            int row = c >> 7;
            int off = c & 127;
            cp16(&ws[c],
                 W1 + (size_t)(rowbase + row) * F + c0 + off * 4,
                 off < nc4);
        }
        if (tid < X_CHUNKS)
            cp16(&xs[tid], g_x + c0 + tid * 4, tid < nc4);
        cp_commit();
    };

    float a0 = 0.f, a1 = 0.f, a2 = 0.f, a3 = 0.f;

    issue(0, t0);
    if (t0 + 1 < t1) issue(1, t0 + 1);

    for (int t = t0; t < t1; t++) {
        int cur = (t - t0) % STG;
        if (t + 1 < t1) asm volatile("cp.async.wait_group 1;");
        else            asm volatile("cp.async.wait_group 0;");
        __syncthreads();
        if (t + 2 < t1) issue((cur + 2) % STG, t + 2);

        const float4* ws = wsb + cur * W_CHUNKS + warp * X_CHUNKS;
        const float4* xs = xsb + cur * X_CHUNKS;
        int c0 = t * CT;
        if (F - c0 >= CT) {
#pragma unroll
            for (int k = 0; k < 4; k++) {
                int i = lane + 32 * k;
                float4 wv = ws[i];
                float4 xv = xs[i];
                a0 = fmaf(wv.x, xv.x, a0);
                a1 = fmaf(wv.y, xv.y, a1);
                a2 = fmaf(wv.z, xv.z, a2);
                a3 = fmaf(wv.w, xv.w, a3);
            }
        } else {
            int nc4 = (F - c0) >> 2;
#pragma unroll
            for (int k = 0; k < 4; k++) {
                int i = lane + 32 * k;
                if (i < nc4) {
                    float4 wv = ws[i];
                    float4 xv = xs[i];
                    a0 = fmaf(wv.x, xv.x, a0);
                    a1 = fmaf(wv.y, xv.y, a1);
                    a2 = fmaf(wv.z, xv.z, a2);
                    a3 = fmaf(wv.w, xv.w, a3);
                }
            }
        }
    }

    float acc = (a0 + a2) + (a1 + a3);
#pragma unroll
    for (int o = 16; o; o >>= 1) acc += __shfl_xor_sync(0xffffffffu, acc, o);
    if (lane == 0) g_partial[cs * H + rowbase + warp] = acc;
}

// ---------------------------------------------------------------------------
// Kernel 3: MLP with latency-flattened layers.
// 1024 threads = 32 warps; warp w owns rows [8w, 8w+8) of each 256x256 layer.
// All 64 loads per warp per layer are independent & coalesced; single shuffle
// phase at the end. W2/W3/W4 prefetched to L2 up front.
// ---------------------------------------------------------------------------
__device__ __forceinline__ void layer256(const float* __restrict__ W,
                                         const float* __restrict__ b,
                                         const float* sa, float* sb,
                                         int warp, int lane) {
    float acc[8];
#pragma unroll
    for (int r = 0; r < 8; r++) acc[r] = 0.f;
    const float* Wb = W + (warp * 8) * H;
#pragma unroll
    for (int k = 0; k < 8; k++) {
        int col = lane + 32 * k;
        float xv = sa[col];
#pragma unroll
        for (int r = 0; r < 8; r++)
            acc[r] = fmaf(Wb[r * H + col], xv, acc[r]);
    }
    // 8 independent shuffle-reduce chains (interleaved by the scheduler)
#pragma unroll
    for (int r = 0; r < 8; r++) {
#pragma unroll
        for (int o = 16; o; o >>= 1)
            acc[r] += __shfl_xor_sync(0xffffffffu, acc[r], o);
    }
    if (lane < 8) {
        int h = warp * 8 + lane;
        sb[h] = tanhf(acc[lane] + b[h]);
    }
}

__global__ void __launch_bounds__(1024) mlp_kernel(const float* __restrict__ b1,
                                                   const float* __restrict__ W2,
                                                   const float* __restrict__ b2,
                                                   const float* __restrict__ W3,
                                                   const float* __restrict__ b3,
                                                   const float* __restrict__ W4,
                                                   float* __restrict__ out) {
    __shared__ float sa[H], sb[H];
    int tid = threadIdx.x;
    int warp = tid >> 5, lane = tid & 31;

    // warm L2 with W2 (64K floats), W3 (64K), W4 (256): 128B lines
    {
        const int LINES = (H * H) / 32;            // 2048 lines per matrix
        for (int i = tid; i < LINES; i += 1024) {
            prefetchL2(W2 + i * 32);
            prefetchL2(W3 + i * 32);
        }
        if (tid < 8) prefetchL2(W4 + tid * 32);
    }

    // fixed-order reduction of GEMV partials (coalesced: [colsplit][row])
    if (tid < H) {
        float acc = 0.f;
#pragma unroll
        for (int k = 0; k < NS; k++) acc += g_partial[k * H + tid];
        sa[tid] = tanhf(acc + b1[tid]);
    }
    __syncthreads();

    layer256(W2, b2, sa, sb, warp, lane);   // sb = tanh(W2@sa + b2)
    __syncthreads();
    layer256(W3, b3, sb, sa, warp, lane);   // sa = tanh(W3@sb + b3)
    __syncthreads();

    if (warp == 0) {
        float a = 0.f;
#pragma unroll
        for (int k = 0; k < 8; k++) a += W4[lane + 32 * k] * sa[lane + 32 * k];
#pragma unroll
        for (int o = 16; o; o >>= 1) a += __shfl_xor_sync(0xffffffffu, a, o);
        if (lane == 0) out[0] = 0.00831446261815324f * 300.0f * a;
    }
}

// ---------------------------------------------------------------------------
extern "C" void kernel_launch(void* const* d_in, const int* in_sizes, int n_in,
                              void* d_out, int out_size) {
    const float* pos  = (const float*)d_in[0];
    const int*   aidx = (const int*)  d_in[1];
    const int*   didx = (const int*)  d_in[2];
    const float* W1   = (const float*)d_in[3];
    const float* b1   = (const float*)d_in[4];
    const float* W2   = (const float*)d_in[5];
    const float* b2   = (const float*)d_in[6];
    const float* W3   = (const float*)d_in[7];
    const float* b3   = (const float*)d_in[8];
    const float* W4   = (const float*)d_in[9];

    int A = in_sizes[1] / 3;
    int D = in_sizes[2] / 4;
    int F = A + 2 * D;
    int nt = A + D;

    cudaFuncSetAttribute(gemv_kernel,
                         cudaFuncAttributeMaxDynamicSharedMemorySize, SMEM_BYTES);

    feat_kernel<<<(nt + 255) / 256, 256>>>(pos, aidx, didx, A, D);

    int TT = (F + CT - 1) / CT;          // 586 tiles for N=100000
    gemv_kernel<<<NRG * NS, 256, SMEM_BYTES>>>(W1, F, TT);

    mlp_kernel<<<1, 1024>>>(b1, W2, b2, W3, b3, W4, (float*)d_out);
}